// round 3
// baseline (speedup 1.0000x reference)
#include <cuda_runtime.h>
#include <cuda_bf16.h>
#include <cstdint>
#include <cstddef>

// Problem constants
#define Bz 64
#define Sq 128
#define Hd 1024
#define Ad 512
#define Ed 512
#define Vv 32000

// Scratch layout (floats)
#define OFF_ENERGY   0u            // 8192*512
#define OFF_DECP     4194304u      // 64*512
#define OFF_SCORE    4227072u      // 64*128
#define OFF_ALPHA    4235264u      // 64*128
#define OFF_CTX      4243456u      // 64*2048
#define OFF_X0       4374528u      // 64*2560
#define OFF_GATES    4538368u      // 64*4096
#define OFF_H0       4800512u      // 64*1024
#define OFF_H1       4866048u      // 64*1024
#define OFF_FCIN     4931584u      // 64*3072
#define SCRATCH_TOTAL 5128192u

__device__ float g_scratch[SCRATCH_TOTAL];

// ---------------------------------------------------------------------------
// tf32 helpers
// ---------------------------------------------------------------------------
__device__ __forceinline__ uint32_t f2tf32(float x) {
    uint32_t r;
    asm("cvt.rna.tf32.f32 %0, %1;" : "=r"(r) : "f"(x));
    return r;
}

__device__ __forceinline__ void mma_tf32(float c[4], const uint32_t a[4], const uint32_t b[2]) {
    asm volatile(
        "mma.sync.aligned.m16n8k8.row.col.f32.tf32.tf32.f32 "
        "{%0,%1,%2,%3}, {%4,%5,%6,%7}, {%8,%9}, {%0,%1,%2,%3};\n"
        : "+f"(c[0]), "+f"(c[1]), "+f"(c[2]), "+f"(c[3])
        : "r"(a[0]), "r"(a[1]), "r"(a[2]), "r"(a[3]), "r"(b[0]), "r"(b[1]));
}

// ---------------------------------------------------------------------------
// Generic tf32 GEMM: C[M,N] = sum_seg A_seg(M,Kseg) * B_seg(N,Kseg)^T (+bias[n])
// All operands row-major with leading dim == K of that segment.
// BM=BN=64, BK=32, 128 threads (4 warps), warp tile 32x32 via m16n8k8.
// Grid: (N/64, M/64)
// ---------------------------------------------------------------------------
#define BK 32
__global__ void __launch_bounds__(128)
gemm_tf32(const float* __restrict__ A,  const float* __restrict__ B,  int K1,
          const float* __restrict__ A2, const float* __restrict__ B2, int K2,
          const float* __restrict__ bias, float* __restrict__ C, int N)
{
    __shared__ uint32_t As[64][BK + 1];
    __shared__ uint32_t Bs[64][BK + 1];

    const int tid  = threadIdx.x;
    const int warp = tid >> 5;
    const int lane = tid & 31;
    const int wm = warp & 1;       // 0/1 -> row half
    const int wn = warp >> 1;      // 0/1 -> col half
    const int g  = lane >> 2;      // groupID 0..7
    const int tg = lane & 3;       // thread-in-group 0..3

    const int m0 = blockIdx.y * 64;
    const int n0 = blockIdx.x * 64;

    float acc[2][4][4];
#pragma unroll
    for (int mi = 0; mi < 2; mi++)
#pragma unroll
        for (int ni = 0; ni < 4; ni++)
#pragma unroll
            for (int r = 0; r < 4; r++) acc[mi][ni][r] = 0.0f;

#pragma unroll 1
    for (int seg = 0; seg < 2; seg++) {
        const float* Ap = seg ? A2 : A;
        const float* Bp = seg ? B2 : B;
        const int K = seg ? K2 : K1;
        if (Ap == nullptr || K == 0) continue;

        for (int k0 = 0; k0 < K; k0 += BK) {
            // load A tile (64x32) and B tile (64x32), convert to tf32
#pragma unroll
            for (int i = 0; i < 4; i++) {
                int id = tid + i * 128;          // 0..511
                int r  = id >> 3;
                int c4 = (id & 7) * 4;
                float4 va = *(const float4*)(Ap + (size_t)(m0 + r) * K + k0 + c4);
                As[r][c4 + 0] = f2tf32(va.x);
                As[r][c4 + 1] = f2tf32(va.y);
                As[r][c4 + 2] = f2tf32(va.z);
                As[r][c4 + 3] = f2tf32(va.w);
                float4 vb = *(const float4*)(Bp + (size_t)(n0 + r) * K + k0 + c4);
                Bs[r][c4 + 0] = f2tf32(vb.x);
                Bs[r][c4 + 1] = f2tf32(vb.y);
                Bs[r][c4 + 2] = f2tf32(vb.z);
                Bs[r][c4 + 3] = f2tf32(vb.w);
            }
            __syncthreads();

#pragma unroll
            for (int ks = 0; ks < BK; ks += 8) {
                uint32_t af[2][4];
                uint32_t bf[4][2];
#pragma unroll
                for (int mi = 0; mi < 2; mi++) {
                    int r = wm * 32 + mi * 16 + g;
                    af[mi][0] = As[r][ks + tg];
                    af[mi][1] = As[r + 8][ks + tg];
                    af[mi][2] = As[r][ks + tg + 4];
                    af[mi][3] = As[r + 8][ks + tg + 4];
                }
#pragma unroll
                for (int ni = 0; ni < 4; ni++) {
                    int cb = wn * 32 + ni * 8 + g;
                    bf[ni][0] = Bs[cb][ks + tg];
                    bf[ni][1] = Bs[cb][ks + tg + 4];
                }
#pragma unroll
                for (int mi = 0; mi < 2; mi++)
#pragma unroll
                    for (int ni = 0; ni < 4; ni++)
                        mma_tf32(acc[mi][ni], af[mi], bf[ni]);
            }
            __syncthreads();
        }
    }

    // epilogue
#pragma unroll
    for (int mi = 0; mi < 2; mi++) {
        int row = m0 + wm * 32 + mi * 16 + g;
#pragma unroll
        for (int ni = 0; ni < 4; ni++) {
            int col = n0 + wn * 32 + ni * 8 + tg * 2;
            float b0 = bias ? bias[col]     : 0.0f;
            float b1 = bias ? bias[col + 1] : 0.0f;
            C[(size_t)row * N + col]           = acc[mi][ni][0] + b0;
            C[(size_t)row * N + col + 1]       = acc[mi][ni][1] + b1;
            C[(size_t)(row + 8) * N + col]     = acc[mi][ni][2] + b0;
            C[(size_t)(row + 8) * N + col + 1] = acc[mi][ni][3] + b1;
        }
    }
}

// ---------------------------------------------------------------------------
// score[b,s] = sum_a tanh(energy[m,a] + dec_proj[b,a]) * v[a], m = s*64+b
// One warp per m; 8 warps/block.
// ---------------------------------------------------------------------------
__global__ void score_kernel(const float* __restrict__ energy,
                             const float* __restrict__ dec_proj,
                             const float* __restrict__ vw,
                             float* __restrict__ score)
{
    int m    = blockIdx.x * 8 + (threadIdx.x >> 5);
    int lane = threadIdx.x & 31;
    int s = m >> 6;
    int b = m & 63;
    const float* e  = energy + (size_t)m * Ad;
    const float* dp = dec_proj + b * Ad;
    float sum = 0.0f;
#pragma unroll 4
    for (int n = lane; n < Ad; n += 32)
        sum += tanhf(e[n] + dp[n]) * vw[n];
#pragma unroll
    for (int o = 16; o; o >>= 1) sum += __shfl_xor_sync(0xffffffffu, sum, o);
    if (lane == 0) score[b * Sq + s] = sum;
}

// ---------------------------------------------------------------------------
// Softmax over S=128 per batch row. 64 blocks x 128 threads.
// ---------------------------------------------------------------------------
__global__ void softmax_kernel(const float* __restrict__ score,
                               float* __restrict__ alpha,
                               float* __restrict__ out_alpha)
{
    int b = blockIdx.x, t = threadIdx.x;
    float x = score[b * Sq + t];
    __shared__ float red[4];

    float m = x;
#pragma unroll
    for (int o = 16; o; o >>= 1) m = fmaxf(m, __shfl_xor_sync(0xffffffffu, m, o));
    if ((t & 31) == 0) red[t >> 5] = m;
    __syncthreads();
    m = fmaxf(fmaxf(red[0], red[1]), fmaxf(red[2], red[3]));
    __syncthreads();

    float e = expf(x - m);
    float ssum = e;
#pragma unroll
    for (int o = 16; o; o >>= 1) ssum += __shfl_xor_sync(0xffffffffu, ssum, o);
    if ((t & 31) == 0) red[t >> 5] = ssum;
    __syncthreads();
    ssum = red[0] + red[1] + red[2] + red[3];

    float a = e / ssum;
    alpha[b * Sq + t] = a;
    out_alpha[b * Sq + t] = a;
}

// ---------------------------------------------------------------------------
// context[b,d] = sum_s alpha[b,s] * enc_out[s,b,d]   (d in 0..2047)
// Grid (2048/256, 64), 256 threads.
// ---------------------------------------------------------------------------
__global__ void context_kernel(const float* __restrict__ alpha,
                               const float* __restrict__ enc,
                               float* __restrict__ ctx)
{
    int b = blockIdx.y;
    int d = blockIdx.x * 256 + threadIdx.x;
    __shared__ float al[Sq];
    if (threadIdx.x < Sq) al[threadIdx.x] = alpha[b * Sq + threadIdx.x];
    __syncthreads();
    const float* e = enc + (size_t)b * 2048 + d;
    float acc = 0.0f;
#pragma unroll 4
    for (int s = 0; s < Sq; s++)
        acc += al[s] * e[(size_t)s * Bz * 2048];
    ctx[b * 2048 + d] = acc;
}

// ---------------------------------------------------------------------------
// x0[b,:512] = emb_table[token[b],:]; x0[b,512:2560] = context[b,:]
// ---------------------------------------------------------------------------
__global__ void build_x0_kernel(const int* __restrict__ token,
                                const float* __restrict__ emb,
                                const float* __restrict__ ctx,
                                float* __restrict__ x0)
{
    int id = blockIdx.x * 256 + threadIdx.x;   // 0..163839
    int b = id / 2560;
    int j = id - b * 2560;
    float v;
    if (j < Ed) v = emb[(size_t)token[b] * Ed + j];
    else        v = ctx[b * 2048 + (j - Ed)];
    x0[id] = v;
}

// ---------------------------------------------------------------------------
// LSTM cell elementwise: gates(64,4096) + biases -> h,c.  65536 threads.
// ---------------------------------------------------------------------------
__device__ __forceinline__ float sigm(float x) { return 1.0f / (1.0f + expf(-x)); }

__global__ void cell_kernel(const float* __restrict__ gates,
                            const float* __restrict__ bih,
                            const float* __restrict__ bhh,
                            const float* __restrict__ c_prev,
                            float* __restrict__ h_scratch,
                            float* __restrict__ h_out,
                            float* __restrict__ c_out)
{
    int id = blockIdx.x * 256 + threadIdx.x;   // 0..65535
    int b = id >> 10;
    int j = id & 1023;
    const float* gr = gates + (size_t)b * 4096;
    float gi = gr[j]        + bih[j]        + bhh[j];
    float gf = gr[1024 + j] + bih[1024 + j] + bhh[1024 + j];
    float gg = gr[2048 + j] + bih[2048 + j] + bhh[2048 + j];
    float go = gr[3072 + j] + bih[3072 + j] + bhh[3072 + j];
    float i = sigm(gi), f = sigm(gf), o = sigm(go);
    float c = f * c_prev[id] + i * tanhf(gg);
    float h = o * tanhf(c);
    h_scratch[id] = h;
    h_out[id] = h;
    c_out[id] = c;
}

// ---------------------------------------------------------------------------
// fcin[b,:1024] = h1[b,:]; fcin[b,1024:3072] = context[b,:]
// ---------------------------------------------------------------------------
__global__ void build_fcin_kernel(const float* __restrict__ h1,
                                  const float* __restrict__ ctx,
                                  float* __restrict__ fcin)
{
    int id = blockIdx.x * 256 + threadIdx.x;   // 0..196607
    int b = id / 3072;
    int j = id - b * 3072;
    float v;
    if (j < Hd) v = h1[b * Hd + j];
    else        v = ctx[b * 2048 + (j - Hd)];
    fcin[id] = v;
}

// ---------------------------------------------------------------------------
// launch
// ---------------------------------------------------------------------------
extern "C" void kernel_launch(void* const* d_in, const int* in_sizes, int n_in,
                              void* d_out, int out_size)
{
    const int*   token  = (const int*)  d_in[0];
    const float* hidden = (const float*)d_in[1];   // (2,64,1024)
    const float* cell   = (const float*)d_in[2];   // (2,64,1024)
    const float* enc    = (const float*)d_in[3];   // (128,64,2048)
    const float* emb    = (const float*)d_in[4];   // (32000,512)
    const float* W_enc  = (const float*)d_in[5];   // (512,2048)
    const float* W_dec  = (const float*)d_in[6];   // (512,1024)
    const float* v_w    = (const float*)d_in[7];   // (512)
    const float* W_ih0  = (const float*)d_in[8];   // (4096,2560)
    const float* W_hh0  = (const float*)d_in[9];   // (4096,1024)
    const float* b_ih0  = (const float*)d_in[10];
    const float* b_hh0  = (const float*)d_in[11];
    const float* W_ih1  = (const float*)d_in[12];  // (4096,1024)
    const float* W_hh1  = (const float*)d_in[13];  // (4096,1024)
    const float* b_ih1  = (const float*)d_in[14];
    const float* b_hh1  = (const float*)d_in[15];
    const float* fc_W   = (const float*)d_in[16];  // (32000,3072)
    const float* fc_b   = (const float*)d_in[17];  // (32000)

    float* scratch = nullptr;
    cudaGetSymbolAddress((void**)&scratch, g_scratch);

    float* energy   = scratch + OFF_ENERGY;
    float* dec_proj = scratch + OFF_DECP;
    float* score    = scratch + OFF_SCORE;
    float* alpha    = scratch + OFF_ALPHA;
    float* ctx      = scratch + OFF_CTX;
    float* x0       = scratch + OFF_X0;
    float* gates    = scratch + OFF_GATES;
    float* h0       = scratch + OFF_H0;
    float* h1       = scratch + OFF_H1;
    float* fcin     = scratch + OFF_FCIN;

    float* out        = (float*)d_out;
    float* out_logits = out;                                   // 64*32000
    float* out_hidden = out + (size_t)Bz * Vv;                 // 2*64*1024
    float* out_cell   = out_hidden + 2 * Bz * Hd;              // 2*64*1024
    float* out_alpha  = out_cell + 2 * Bz * Hd;                // 64*128

    // 1) dec_proj = hidden[-1] @ W_dec^T              (64,512)
    gemm_tf32<<<dim3(Ad / 64, 1), 128>>>(hidden + (size_t)Bz * Hd, W_dec, Hd,
                                         nullptr, nullptr, 0, nullptr, dec_proj, Ad);
    // 2) energy = enc @ W_enc^T                       (8192,512)
    gemm_tf32<<<dim3(Ad / 64, (Sq * Bz) / 64), 128>>>(enc, W_enc, 2 * Hd,
                                                      nullptr, nullptr, 0, nullptr, energy, Ad);
    // 3) score
    score_kernel<<<(Sq * Bz) / 8, 256>>>(energy, dec_proj, v_w, score);
    // 4) softmax -> alpha (scratch + output)
    softmax_kernel<<<Bz, Sq>>>(score, alpha, out_alpha);
    // 5) context
    context_kernel<<<dim3(2048 / 256, Bz), 256>>>(alpha, enc, ctx);
    // 6) x0 = [embedded | context]
    build_x0_kernel<<<(Bz * 2560) / 256, 256>>>(token, emb, ctx, x0);
    // 7) gates0 = x0 @ W_ih0^T + hidden[0] @ W_hh0^T  (64,4096)
    gemm_tf32<<<dim3(4096 / 64, 1), 128>>>(x0, W_ih0, Ed + 2 * Hd,
                                           hidden, W_hh0, Hd, nullptr, gates, 4096);
    // 8) LSTM cell 0 -> h0, c0
    cell_kernel<<<(Bz * Hd) / 256, 256>>>(gates, b_ih0, b_hh0, cell,
                                          h0, out_hidden, out_cell);
    // 9) gates1 = h0 @ W_ih1^T + hidden[1] @ W_hh1^T
    gemm_tf32<<<dim3(4096 / 64, 1), 128>>>(h0, W_ih1, Hd,
                                           hidden + (size_t)Bz * Hd, W_hh1, Hd,
                                           nullptr, gates, 4096);
    // 10) LSTM cell 1 -> h1, c1
    cell_kernel<<<(Bz * Hd) / 256, 256>>>(gates, b_ih1, b_hh1, cell + (size_t)Bz * Hd,
                                          h1, out_hidden + (size_t)Bz * Hd,
                                          out_cell + (size_t)Bz * Hd);
    // 11) fcin = [h1 | context]
    build_fcin_kernel<<<(Bz * 3 * Hd) / 256, 256>>>(h1, ctx, fcin);
    // 12) logits = fcin @ fc_W^T + fc_b              (64,32000)
    gemm_tf32<<<dim3(Vv / 64, 1), 128>>>(fcin, fc_W, 3 * Hd,
                                         nullptr, nullptr, 0, fc_b, out_logits, Vv);
}

// round 5
// speedup vs baseline: 2.2773x; 2.2773x over previous
#include <cuda_runtime.h>
#include <cuda_bf16.h>
#include <cstdint>
#include <cstddef>

// Problem constants
#define Bz 64
#define Sq 128
#define Hd 1024
#define Ad 512
#define Ed 512
#define Vv 32000

// Scratch layout (floats)
#define OFF_ENERGY   0u            // 8192*512
#define OFF_DECP     4194304u      // 64*512
#define OFF_SCORE    4227072u      // 64*128
#define OFF_ALPHA    4235264u      // 64*128
#define OFF_CTX      4243456u      // 64*2048
#define OFF_X0       4374528u      // 64*2560
#define OFF_GATES    4538368u      // 64*4096
#define OFF_H0       4800512u      // 64*1024
#define OFF_H1       4866048u      // 64*1024
#define OFF_FCIN     4931584u      // 64*3072
#define SCRATCH_TOTAL 5128192u

__device__ float g_scratch[SCRATCH_TOTAL];

#define BK 32
#define LDSW (BK + 4)   // padded smem row (floats); 144B row stride, 16B aligned

// ---------------------------------------------------------------------------
// tf32 / cp.async helpers
// ---------------------------------------------------------------------------
__device__ __forceinline__ uint32_t f2tf32(float x) {
    uint32_t r;
    asm("cvt.rna.tf32.f32 %0, %1;" : "=r"(r) : "f"(x));
    return r;
}

__device__ __forceinline__ void mma_tf32(float c[4], const uint32_t a[4], const uint32_t b[2]) {
    asm volatile(
        "mma.sync.aligned.m16n8k8.row.col.f32.tf32.tf32.f32 "
        "{%0,%1,%2,%3}, {%4,%5,%6,%7}, {%8,%9}, {%0,%1,%2,%3};\n"
        : "+f"(c[0]), "+f"(c[1]), "+f"(c[2]), "+f"(c[3])
        : "r"(a[0]), "r"(a[1]), "r"(a[2]), "r"(a[3]), "r"(b[0]), "r"(b[1]));
}

__device__ __forceinline__ void cp16(float* dst_smem, const float* src_gmem) {
    uint32_t sm = (uint32_t)__cvta_generic_to_shared(dst_smem);
    asm volatile("cp.async.cg.shared.global [%0], [%1], 16;\n" :: "r"(sm), "l"(src_gmem));
}
__device__ __forceinline__ void cp_commit() {
    asm volatile("cp.async.commit_group;\n");
}
__device__ __forceinline__ void cp_wait1() {
    asm volatile("cp.async.wait_group 1;\n");
}

// ---------------------------------------------------------------------------
// Pipelined tf32 GEMM: C[M,N] = sum_seg A_seg(M,Kseg) * B_seg(N,Kseg)^T (+bias)
// Row-major operands, leading dim == K of segment. 3-stage cp.async pipeline.
// 256 threads = 8 warps. Warp tile: 32 x WN. Requires (BM/32)*(BN/WN) == 8.
// Grid: (N/BN, M/BM). M % BM == 0, N % BN == 0, K % BK == 0 (both segments).
// ---------------------------------------------------------------------------
template<int BM, int BN, int WN, int STAGES>
__global__ void __launch_bounds__(256, 1)
gemm_cp(const float* __restrict__ A,  const float* __restrict__ B,  int K1,
        const float* __restrict__ A2, const float* __restrict__ B2, int K2,
        const float* __restrict__ bias, float* __restrict__ C, int N)
{
    constexpr int NWM = BM / 32;
    constexpr int NI  = WN / 8;
    constexpr int STAGE_F = (BM + BN) * LDSW;   // floats per stage

    extern __shared__ float smem[];

    const int tid  = threadIdx.x;
    const int warp = tid >> 5;
    const int lane = tid & 31;
    const int wm = warp % NWM;
    const int wn = warp / NWM;
    const int g  = lane >> 2;
    const int tg = lane & 3;

    const int m0 = blockIdx.y * BM;
    const int n0 = blockIdx.x * BN;

    float acc[2][NI][4];
#pragma unroll
    for (int mi = 0; mi < 2; mi++)
#pragma unroll
        for (int ni = 0; ni < NI; ni++)
#pragma unroll
            for (int r = 0; r < 4; r++) acc[mi][ni][r] = 0.0f;

    const int T1 = K1 / BK;
    const int T  = T1 + ((A2 != nullptr) ? (K2 / BK) : 0);

    // stage loader: tile index t -> slot t % STAGES
    auto load_stage = [&](int t) {
        const float* Ap; const float* Bp; int ld, off;
        if (t < T1) { Ap = A;  Bp = B;  ld = K1; off = t * BK; }
        else        { Ap = A2; Bp = B2; ld = K2; off = (t - T1) * BK; }
        float* as = smem + (t % STAGES) * STAGE_F;
        float* bs = as + BM * LDSW;
#pragma unroll
        for (int i = 0; i < BM / 32; i++) {
            int id = tid + i * 256;            // BM*8 float4 chunks
            int r  = id >> 3;
            int c4 = (id & 7) * 4;
            cp16(as + r * LDSW + c4, Ap + (size_t)(m0 + r) * ld + off + c4);
        }
#pragma unroll
        for (int i = 0; i < BN / 32; i++) {
            int id = tid + i * 256;
            int r  = id >> 3;
            int c4 = (id & 7) * 4;
            cp16(bs + r * LDSW + c4, Bp + (size_t)(n0 + r) * ld + off + c4);
        }
        cp_commit();
    };

    // prologue: stages 0..STAGES-2
#pragma unroll
    for (int s = 0; s < STAGES - 1; s++) {
        if (s < T) load_stage(s); else cp_commit();
    }

    for (int t = 0; t < T; t++) {
        cp_wait1();           // with empty-group commits, stage t is complete
        __syncthreads();      // everyone done computing stage t-1's slot reuse target

        int nt = t + STAGES - 1;
        if (nt < T) load_stage(nt); else cp_commit();

        const float* as = smem + (t % STAGES) * STAGE_F;
        const float* bs = as + BM * LDSW;

#pragma unroll
        for (int ks = 0; ks < BK; ks += 8) {
            uint32_t af[2][4];
            uint32_t bf[NI][2];
#pragma unroll
            for (int mi = 0; mi < 2; mi++) {
                int r = wm * 32 + mi * 16 + g;
                af[mi][0] = f2tf32(as[r * LDSW + ks + tg]);
                af[mi][1] = f2tf32(as[(r + 8) * LDSW + ks + tg]);
                af[mi][2] = f2tf32(as[r * LDSW + ks + tg + 4]);
                af[mi][3] = f2tf32(as[(r + 8) * LDSW + ks + tg + 4]);
            }
#pragma unroll
            for (int ni = 0; ni < NI; ni++) {
                int cb = wn * WN + ni * 8 + g;
                bf[ni][0] = f2tf32(bs[cb * LDSW + ks + tg]);
                bf[ni][1] = f2tf32(bs[cb * LDSW + ks + tg + 4]);
            }
#pragma unroll
            for (int mi = 0; mi < 2; mi++)
#pragma unroll
                for (int ni = 0; ni < NI; ni++)
                    mma_tf32(acc[mi][ni], af[mi], bf[ni]);
        }
    }

    // epilogue
#pragma unroll
    for (int mi = 0; mi < 2; mi++) {
        int row = m0 + wm * 32 + mi * 16 + g;
#pragma unroll
        for (int ni = 0; ni < NI; ni++) {
            int col = n0 + wn * WN + ni * 8 + tg * 2;
            float b0 = bias ? bias[col]     : 0.0f;
            float b1 = bias ? bias[col + 1] : 0.0f;
            C[(size_t)row * N + col]           = acc[mi][ni][0] + b0;
            C[(size_t)row * N + col + 1]       = acc[mi][ni][1] + b1;
            C[(size_t)(row + 8) * N + col]     = acc[mi][ni][2] + b0;
            C[(size_t)(row + 8) * N + col + 1] = acc[mi][ni][3] + b1;
        }
    }
}

// Instantiations
using GemmBig   = void(*)(const float*, const float*, int, const float*, const float*, int,
                          const float*, float*, int);
#define GEMM_ENERGY gemm_cp<128,128,64,3>
#define GEMM_SMALL  gemm_cp<64,128,32,3>
#define SMEM_ENERGY ((128 + 128) * LDSW * 4 * 3)
#define SMEM_SMALL  ((64 + 128) * LDSW * 4 * 3)

// ---------------------------------------------------------------------------
// score[b,s] = sum_a tanh(energy[m,a] + dec_proj[b,a]) * v[a], m = s*64+b
// ---------------------------------------------------------------------------
__global__ void score_kernel(const float* __restrict__ energy,
                             const float* __restrict__ dec_proj,
                             const float* __restrict__ vw,
                             float* __restrict__ score)
{
    int m    = blockIdx.x * 8 + (threadIdx.x >> 5);
    int lane = threadIdx.x & 31;
    int s = m >> 6;
    int b = m & 63;
    const float* e  = energy + (size_t)m * Ad;
    const float* dp = dec_proj + b * Ad;
    float sum = 0.0f;
#pragma unroll 4
    for (int n = lane; n < Ad; n += 32)
        sum += tanhf(e[n] + dp[n]) * vw[n];
#pragma unroll
    for (int o = 16; o; o >>= 1) sum += __shfl_xor_sync(0xffffffffu, sum, o);
    if (lane == 0) score[b * Sq + s] = sum;
}

// ---------------------------------------------------------------------------
// Softmax over S=128 per batch row.
// ---------------------------------------------------------------------------
__global__ void softmax_kernel(const float* __restrict__ score,
                               float* __restrict__ alpha,
                               float* __restrict__ out_alpha)
{
    int b = blockIdx.x, t = threadIdx.x;
    float x = score[b * Sq + t];
    __shared__ float red[4];

    float m = x;
#pragma unroll
    for (int o = 16; o; o >>= 1) m = fmaxf(m, __shfl_xor_sync(0xffffffffu, m, o));
    if ((t & 31) == 0) red[t >> 5] = m;
    __syncthreads();
    m = fmaxf(fmaxf(red[0], red[1]), fmaxf(red[2], red[3]));
    __syncthreads();

    float e = expf(x - m);
    float ssum = e;
#pragma unroll
    for (int o = 16; o; o >>= 1) ssum += __shfl_xor_sync(0xffffffffu, ssum, o);
    if ((t & 31) == 0) red[t >> 5] = ssum;
    __syncthreads();
    ssum = red[0] + red[1] + red[2] + red[3];

    float a = e / ssum;
    alpha[b * Sq + t] = a;
    out_alpha[b * Sq + t] = a;
}

// ---------------------------------------------------------------------------
// context[b,d] = sum_s alpha[b,s] * enc_out[s,b,d]
// ---------------------------------------------------------------------------
__global__ void context_kernel(const float* __restrict__ alpha,
                               const float* __restrict__ enc,
                               float* __restrict__ ctx)
{
    int b = blockIdx.y;
    int d = blockIdx.x * 256 + threadIdx.x;
    __shared__ float al[Sq];
    if (threadIdx.x < Sq) al[threadIdx.x] = alpha[b * Sq + threadIdx.x];
    __syncthreads();
    const float* e = enc + (size_t)b * 2048 + d;
    float acc = 0.0f;
#pragma unroll 4
    for (int s = 0; s < Sq; s++)
        acc += al[s] * e[(size_t)s * Bz * 2048];
    ctx[b * 2048 + d] = acc;
}

// ---------------------------------------------------------------------------
// x0[b,:512] = emb_table[token[b],:]; x0[b,512:2560] = context[b,:]
// ---------------------------------------------------------------------------
__global__ void build_x0_kernel(const int* __restrict__ token,
                                const float* __restrict__ emb,
                                const float* __restrict__ ctx,
                                float* __restrict__ x0)
{
    int id = blockIdx.x * 256 + threadIdx.x;
    int b = id / 2560;
    int j = id - b * 2560;
    float v;
    if (j < Ed) v = emb[(size_t)token[b] * Ed + j];
    else        v = ctx[b * 2048 + (j - Ed)];
    x0[id] = v;
}

// ---------------------------------------------------------------------------
// LSTM cell elementwise
// ---------------------------------------------------------------------------
__device__ __forceinline__ float sigm(float x) { return 1.0f / (1.0f + expf(-x)); }

__global__ void cell_kernel(const float* __restrict__ gates,
                            const float* __restrict__ bih,
                            const float* __restrict__ bhh,
                            const float* __restrict__ c_prev,
                            float* __restrict__ h_scratch,
                            float* __restrict__ h_out,
                            float* __restrict__ c_out)
{
    int id = blockIdx.x * 256 + threadIdx.x;
    int b = id >> 10;
    int j = id & 1023;
    const float* gr = gates + (size_t)b * 4096;
    float gi = gr[j]        + bih[j]        + bhh[j];
    float gf = gr[1024 + j] + bih[1024 + j] + bhh[1024 + j];
    float gg = gr[2048 + j] + bih[2048 + j] + bhh[2048 + j];
    float go = gr[3072 + j] + bih[3072 + j] + bhh[3072 + j];
    float i = sigm(gi), f = sigm(gf), o = sigm(go);
    float c = f * c_prev[id] + i * tanhf(gg);
    float h = o * tanhf(c);
    h_scratch[id] = h;
    h_out[id] = h;
    c_out[id] = c;
}

// ---------------------------------------------------------------------------
// fcin[b,:1024] = h1[b,:]; fcin[b,1024:3072] = context[b,:]
// ---------------------------------------------------------------------------
__global__ void build_fcin_kernel(const float* __restrict__ h1,
                                  const float* __restrict__ ctx,
                                  float* __restrict__ fcin)
{
    int id = blockIdx.x * 256 + threadIdx.x;
    int b = id / 3072;
    int j = id - b * 3072;
    float v;
    if (j < Hd) v = h1[b * Hd + j];
    else        v = ctx[b * 2048 + (j - Hd)];
    fcin[id] = v;
}

// ---------------------------------------------------------------------------
// launch
// ---------------------------------------------------------------------------
extern "C" void kernel_launch(void* const* d_in, const int* in_sizes, int n_in,
                              void* d_out, int out_size)
{
    const int*   token  = (const int*)  d_in[0];
    const float* hidden = (const float*)d_in[1];   // (2,64,1024)
    const float* cell   = (const float*)d_in[2];   // (2,64,1024)
    const float* enc    = (const float*)d_in[3];   // (128,64,2048)
    const float* emb    = (const float*)d_in[4];   // (32000,512)
    const float* W_enc  = (const float*)d_in[5];   // (512,2048)
    const float* W_dec  = (const float*)d_in[6];   // (512,1024)
    const float* v_w    = (const float*)d_in[7];   // (512)
    const float* W_ih0  = (const float*)d_in[8];   // (4096,2560)
    const float* W_hh0  = (const float*)d_in[9];   // (4096,1024)
    const float* b_ih0  = (const float*)d_in[10];
    const float* b_hh0  = (const float*)d_in[11];
    const float* W_ih1  = (const float*)d_in[12];  // (4096,1024)
    const float* W_hh1  = (const float*)d_in[13];  // (4096,1024)
    const float* b_ih1  = (const float*)d_in[14];
    const float* b_hh1  = (const float*)d_in[15];
    const float* fc_W   = (const float*)d_in[16];  // (32000,3072)
    const float* fc_b   = (const float*)d_in[17];  // (32000)

    float* scratch = nullptr;
    cudaGetSymbolAddress((void**)&scratch, g_scratch);

    float* energy   = scratch + OFF_ENERGY;
    float* dec_proj = scratch + OFF_DECP;
    float* score    = scratch + OFF_SCORE;
    float* alpha    = scratch + OFF_ALPHA;
    float* ctx      = scratch + OFF_CTX;
    float* x0       = scratch + OFF_X0;
    float* gates    = scratch + OFF_GATES;
    float* h0       = scratch + OFF_H0;
    float* h1       = scratch + OFF_H1;
    float* fcin     = scratch + OFF_FCIN;

    float* out        = (float*)d_out;
    float* out_logits = out;                                   // 64*32000
    float* out_hidden = out + (size_t)Bz * Vv;                 // 2*64*1024
    float* out_cell   = out_hidden + 2 * Bz * Hd;              // 2*64*1024
    float* out_alpha  = out_cell + 2 * Bz * Hd;                // 64*128

    // Allow >48KB dynamic smem (host-side, idempotent, capture-safe)
    cudaFuncSetAttribute(GEMM_ENERGY, cudaFuncAttributeMaxDynamicSharedMemorySize, SMEM_ENERGY);
    cudaFuncSetAttribute(GEMM_SMALL,  cudaFuncAttributeMaxDynamicSharedMemorySize, SMEM_SMALL);

    // 1) dec_proj = hidden[-1] @ W_dec^T              (64,512)
    GEMM_SMALL<<<dim3(Ad / 128, 1), 256, SMEM_SMALL>>>(
        hidden + (size_t)Bz * Hd, W_dec, Hd,
        nullptr, nullptr, 0, nullptr, dec_proj, Ad);
    // 2) energy = enc @ W_enc^T                       (8192,512)
    GEMM_ENERGY<<<dim3(Ad / 128, (Sq * Bz) / 128), 256, SMEM_ENERGY>>>(
        enc, W_enc, 2 * Hd,
        nullptr, nullptr, 0, nullptr, energy, Ad);
    // 3) score
    score_kernel<<<(Sq * Bz) / 8, 256>>>(energy, dec_proj, v_w, score);
    // 4) softmax -> alpha (scratch + output)
    softmax_kernel<<<Bz, Sq>>>(score, alpha, out_alpha);
    // 5) context
    context_kernel<<<dim3(2048 / 256, Bz), 256>>>(alpha, enc, ctx);
    // 6) x0 = [embedded | context]
    build_x0_kernel<<<(Bz * 2560) / 256, 256>>>(token, emb, ctx, x0);
    // 7) gates0 = x0 @ W_ih0^T + hidden[0] @ W_hh0^T  (64,4096)
    GEMM_SMALL<<<dim3(4096 / 128, 1), 256, SMEM_SMALL>>>(
        x0, W_ih0, Ed + 2 * Hd,
        hidden, W_hh0, Hd, nullptr, gates, 4096);
    // 8) LSTM cell 0 -> h0, c0
    cell_kernel<<<(Bz * Hd) / 256, 256>>>(gates, b_ih0, b_hh0, cell,
                                          h0, out_hidden, out_cell);
    // 9) gates1 = h0 @ W_ih1^T + hidden[1] @ W_hh1^T
    GEMM_SMALL<<<dim3(4096 / 128, 1), 256, SMEM_SMALL>>>(
        h0, W_ih1, Hd,
        hidden + (size_t)Bz * Hd, W_hh1, Hd, nullptr, gates, 4096);
    // 10) LSTM cell 1 -> h1, c1
    cell_kernel<<<(Bz * Hd) / 256, 256>>>(gates, b_ih1, b_hh1, cell + (size_t)Bz * Hd,
                                          h1, out_hidden + (size_t)Bz * Hd,
                                          out_cell + (size_t)Bz * Hd);
    // 11) fcin = [h1 | context]
    build_fcin_kernel<<<(Bz * 3 * Hd) / 256, 256>>>(h1, ctx, fcin);
    // 12) logits = fcin @ fc_W^T + fc_b              (64,32000)
    GEMM_SMALL<<<dim3(Vv / 128, 1), 256, SMEM_SMALL>>>(
        fcin, fc_W, 3 * Hd,
        nullptr, nullptr, 0, fc_b, out_logits, Vv);
}

// round 6
// speedup vs baseline: 2.9073x; 1.2767x over previous
#include <cuda_runtime.h>
#include <cuda_bf16.h>
#include <cstdint>
#include <cstddef>
#include <math_constants.h>

// Problem constants
#define Bz 64
#define Sq 128
#define Hd 1024
#define Ad 512
#define Ed 512
#define Vv 32000

#define NSPLIT 8      // split-K for gates GEMMs
#define DPSPLIT 4     // split-K for dec_proj

// Scratch layout (floats)
#define OFF_ENERGY   0u                       // 8192*512            = 4194304
#define OFF_DECP     4194304u                 // DPSPLIT*64*512      = 131072
#define OFF_ALPHA    4325376u                 // 64*128              = 8192
#define OFF_X0       4333568u                 // 64*2560             = 163840
#define OFF_GATES    4497408u                 // NSPLIT*64*4096      = 2097152
#define OFF_H0       6594560u                 // 64*1024             = 65536
#define OFF_FCIN     6660096u                 // 64*3072             = 196608
#define SCRATCH_TOTAL 6856704u

__device__ float g_scratch[SCRATCH_TOTAL];

#define BK 32
#define LDSW (BK + 4)   // padded smem row (floats)

// ---------------------------------------------------------------------------
// helpers
// ---------------------------------------------------------------------------
__device__ __forceinline__ uint32_t f2tf32(float x) {
    uint32_t r;
    asm("cvt.rna.tf32.f32 %0, %1;" : "=r"(r) : "f"(x));
    return r;
}

__device__ __forceinline__ float tanh_fast(float x) {
    float y;
    asm("tanh.approx.f32 %0, %1;" : "=f"(y) : "f"(x));
    return y;
}

__device__ __forceinline__ void mma_tf32(float c[4], const uint32_t a[4], const uint32_t b[2]) {
    asm volatile(
        "mma.sync.aligned.m16n8k8.row.col.f32.tf32.tf32.f32 "
        "{%0,%1,%2,%3}, {%4,%5,%6,%7}, {%8,%9}, {%0,%1,%2,%3};\n"
        : "+f"(c[0]), "+f"(c[1]), "+f"(c[2]), "+f"(c[3])
        : "r"(a[0]), "r"(a[1]), "r"(a[2]), "r"(a[3]), "r"(b[0]), "r"(b[1]));
}

__device__ __forceinline__ void cp16(float* dst_smem, const float* src_gmem) {
    uint32_t sm = (uint32_t)__cvta_generic_to_shared(dst_smem);
    asm volatile("cp.async.cg.shared.global [%0], [%1], 16;\n" :: "r"(sm), "l"(src_gmem));
}
__device__ __forceinline__ void cp_commit() {
    asm volatile("cp.async.commit_group;\n");
}
__device__ __forceinline__ void cp_wait1() {
    asm volatile("cp.async.wait_group 1;\n");
}

// ---------------------------------------------------------------------------
// Pipelined tf32 GEMM with optional split-K over tile range.
// C[M,N] = sum_seg A_seg(M,Kseg) * B_seg(N,Kseg)^T (+bias). Row-major, ld==K.
// blockIdx.z selects tile range [z*tpz, min(T,(z+1)*tpz)), output offset
// z*zstride (partials summed by a downstream kernel when gridDim.z > 1).
// 256 threads = 8 warps; warp tile 32 x WN; (BM/32)*(BN/WN) == 8.
// ---------------------------------------------------------------------------
template<int BM, int BN, int WN, int STAGES>
__global__ void __launch_bounds__(256, 1)
gemm_cp(const float* __restrict__ A,  const float* __restrict__ B,  int K1,
        const float* __restrict__ A2, const float* __restrict__ B2, int K2,
        const float* __restrict__ bias, float* __restrict__ C, int N,
        int tpz, int zstride)
{
    constexpr int NWM = BM / 32;
    constexpr int NI  = WN / 8;
    constexpr int STAGE_F = (BM + BN) * LDSW;

    extern __shared__ float smem[];

    const int tid  = threadIdx.x;
    const int warp = tid >> 5;
    const int lane = tid & 31;
    const int wm = warp % NWM;
    const int wn = warp / NWM;
    const int g  = lane >> 2;
    const int tg = lane & 3;

    const int m0 = blockIdx.y * BM;
    const int n0 = blockIdx.x * BN;

    C += (size_t)blockIdx.z * zstride;

    float acc[2][NI][4];
#pragma unroll
    for (int mi = 0; mi < 2; mi++)
#pragma unroll
        for (int ni = 0; ni < NI; ni++)
#pragma unroll
            for (int r = 0; r < 4; r++) acc[mi][ni][r] = 0.0f;

    const int T1 = K1 / BK;
    const int T  = T1 + ((A2 != nullptr) ? (K2 / BK) : 0);
    const int tb = blockIdx.z * tpz;
    const int te = (tb + tpz < T) ? (tb + tpz) : T;

    auto load_stage = [&](int t) {
        const float* Ap; const float* Bp; int ld, off;
        if (t < T1) { Ap = A;  Bp = B;  ld = K1; off = t * BK; }
        else        { Ap = A2; Bp = B2; ld = K2; off = (t - T1) * BK; }
        float* as = smem + (t % STAGES) * STAGE_F;
        float* bs = as + BM * LDSW;
#pragma unroll
        for (int i = 0; i < BM / 32; i++) {
            int id = tid + i * 256;
            int r  = id >> 3;
            int c4 = (id & 7) * 4;
            cp16(as + r * LDSW + c4, Ap + (size_t)(m0 + r) * ld + off + c4);
        }
#pragma unroll
        for (int i = 0; i < BN / 32; i++) {
            int id = tid + i * 256;
            int r  = id >> 3;
            int c4 = (id & 7) * 4;
            cp16(bs + r * LDSW + c4, Bp + (size_t)(n0 + r) * ld + off + c4);
        }
        cp_commit();
    };

#pragma unroll
    for (int s = 0; s < STAGES - 1; s++) {
        if (tb + s < te) load_stage(tb + s); else cp_commit();
    }

    for (int t = tb; t < te; t++) {
        cp_wait1();
        __syncthreads();

        int nt = t + STAGES - 1;
        if (nt < te) load_stage(nt); else cp_commit();

        const float* as = smem + (t % STAGES) * STAGE_F;
        const float* bs = as + BM * LDSW;

#pragma unroll
        for (int ks = 0; ks < BK; ks += 8) {
            uint32_t af[2][4];
            uint32_t bf[NI][2];
#pragma unroll
            for (int mi = 0; mi < 2; mi++) {
                int r = wm * 32 + mi * 16 + g;
                af[mi][0] = f2tf32(as[r * LDSW + ks + tg]);
                af[mi][1] = f2tf32(as[(r + 8) * LDSW + ks + tg]);
                af[mi][2] = f2tf32(as[r * LDSW + ks + tg + 4]);
                af[mi][3] = f2tf32(as[(r + 8) * LDSW + ks + tg + 4]);
            }
#pragma unroll
            for (int ni = 0; ni < NI; ni++) {
                int cb = wn * WN + ni * 8 + g;
                bf[ni][0] = f2tf32(bs[cb * LDSW + ks + tg]);
                bf[ni][1] = f2tf32(bs[cb * LDSW + ks + tg + 4]);
            }
#pragma unroll
            for (int mi = 0; mi < 2; mi++)
#pragma unroll
                for (int ni = 0; ni < NI; ni++)
                    mma_tf32(acc[mi][ni], af[mi], bf[ni]);
        }
    }

#pragma unroll
    for (int mi = 0; mi < 2; mi++) {
        int row = m0 + wm * 32 + mi * 16 + g;
#pragma unroll
        for (int ni = 0; ni < NI; ni++) {
            int col = n0 + wn * WN + ni * 8 + tg * 2;
            float b0 = bias ? bias[col]     : 0.0f;
            float b1 = bias ? bias[col + 1] : 0.0f;
            C[(size_t)row * N + col]           = acc[mi][ni][0] + b0;
            C[(size_t)row * N + col + 1]       = acc[mi][ni][1] + b1;
            C[(size_t)(row + 8) * N + col]     = acc[mi][ni][2] + b0;
            C[(size_t)(row + 8) * N + col + 1] = acc[mi][ni][3] + b1;
        }
    }
}

#define GEMM_ENERGY gemm_cp<128,128,64,3>
#define GEMM_SMALL  gemm_cp<64,128,32,3>
#define SMEM_ENERGY ((128 + 128) * LDSW * 4 * 3)
#define SMEM_SMALL  ((64 + 128) * LDSW * 4 * 3)

// ---------------------------------------------------------------------------
// Fused score + softmax. Grid: 64 (one block per batch row), 256 threads.
// score[s] = sum_a tanh(energy[(s*64+b),a] + dp[b,a]) * v[a]; dp summed from
// DPSPLIT partials. Then softmax over s=0..127 -> alpha (scratch + output).
// ---------------------------------------------------------------------------
__global__ void __launch_bounds__(256)
score_softmax_kernel(const float* __restrict__ energy,
                     const float* __restrict__ dp_parts,
                     const float* __restrict__ vw,
                     float* __restrict__ alpha,
                     float* __restrict__ out_alpha)
{
    __shared__ float dps[Ad];
    __shared__ float vs[Ad];
    __shared__ float sc[Sq];
    __shared__ float red[8];

    const int b    = blockIdx.x;
    const int tid  = threadIdx.x;
    const int warp = tid >> 5;
    const int lane = tid & 31;

    for (int i = tid; i < Ad; i += 256) {
        float s = 0.0f;
#pragma unroll
        for (int z = 0; z < DPSPLIT; z++)
            s += dp_parts[z * (Bz * Ad) + b * Ad + i];
        dps[i] = s;
        vs[i] = vw[i];
    }
    __syncthreads();

    // 8 warps x 16 s-values each
    for (int si = 0; si < 16; si++) {
        int s = warp * 16 + si;
        const float* e = energy + ((size_t)s * Bz + b) * Ad;
        float sum = 0.0f;
#pragma unroll 4
        for (int n = lane; n < Ad; n += 32)
            sum += tanh_fast(e[n] + dps[n]) * vs[n];
#pragma unroll
        for (int o = 16; o; o >>= 1) sum += __shfl_xor_sync(0xffffffffu, sum, o);
        if (lane == 0) sc[s] = sum;
    }
    __syncthreads();

    // softmax over sc[0..127] with all 256 threads participating in reductions
    float x = (tid < Sq) ? sc[tid] : -CUDART_INF_F;
    float m = x;
#pragma unroll
    for (int o = 16; o; o >>= 1) m = fmaxf(m, __shfl_xor_sync(0xffffffffu, m, o));
    if (lane == 0) red[warp] = m;
    __syncthreads();
    m = red[0];
#pragma unroll
    for (int w = 1; w < 8; w++) m = fmaxf(m, red[w]);
    __syncthreads();

    float e = (tid < Sq) ? __expf(x - m) : 0.0f;
    float ssum = e;
#pragma unroll
    for (int o = 16; o; o >>= 1) ssum += __shfl_xor_sync(0xffffffffu, ssum, o);
    if (lane == 0) red[warp] = ssum;
    __syncthreads();
    ssum = red[0];
#pragma unroll
    for (int w = 1; w < 8; w++) ssum += red[w];

    if (tid < Sq) {
        float a = e / ssum;
        alpha[b * Sq + tid] = a;
        out_alpha[b * Sq + tid] = a;
    }
}

// ---------------------------------------------------------------------------
// context[b,d] = sum_s alpha[b,s] * enc_out[s,b,d]; written straight into the
// x0 slot (cols 512..2559) and the fcin slot (cols 1024..3071).
// Grid (2048/256, 64), 256 threads.
// ---------------------------------------------------------------------------
__global__ void context_kernel(const float* __restrict__ alpha,
                               const float* __restrict__ enc,
                               float* __restrict__ x0,
                               float* __restrict__ fcin)
{
    int b = blockIdx.y;
    int d = blockIdx.x * 256 + threadIdx.x;
    __shared__ float al[Sq];
    if (threadIdx.x < Sq) al[threadIdx.x] = alpha[b * Sq + threadIdx.x];
    __syncthreads();
    const float* e = enc + (size_t)b * 2048 + d;
    float acc = 0.0f;
#pragma unroll 4
    for (int s = 0; s < Sq; s++)
        acc += al[s] * e[(size_t)s * Bz * 2048];
    x0[b * 2560 + Ed + d]    = acc;
    fcin[b * 3072 + Hd + d]  = acc;
}

// ---------------------------------------------------------------------------
// x0[b,:512] = emb_table[token[b],:]
// ---------------------------------------------------------------------------
__global__ void embed_kernel(const int* __restrict__ token,
                             const float* __restrict__ emb,
                             float* __restrict__ x0)
{
    int id = blockIdx.x * 256 + threadIdx.x;   // 0..32767
    int b = id >> 9;
    int j = id & 511;
    x0[b * 2560 + j] = emb[(size_t)token[b] * Ed + j];
}

// ---------------------------------------------------------------------------
// LSTM cell elementwise; sums NSPLIT gate partials, adds biases.
// h written to h_scratch (stride h_stride) and to out_hidden; c to out_cell.
// ---------------------------------------------------------------------------
__device__ __forceinline__ float sigm(float x) { return 1.0f / (1.0f + __expf(-x)); }

__global__ void cell_kernel(const float* __restrict__ gates,
                            const float* __restrict__ bih,
                            const float* __restrict__ bhh,
                            const float* __restrict__ c_prev,
                            float* __restrict__ h_scratch, int h_stride,
                            float* __restrict__ h_out,
                            float* __restrict__ c_out)
{
    int id = blockIdx.x * 256 + threadIdx.x;   // 0..65535
    int b = id >> 10;
    int j = id & 1023;
    float gi = bih[j]        + bhh[j];
    float gf = bih[1024 + j] + bhh[1024 + j];
    float gg = bih[2048 + j] + bhh[2048 + j];
    float go = bih[3072 + j] + bhh[3072 + j];
#pragma unroll
    for (int z = 0; z < NSPLIT; z++) {
        const float* gr = gates + (size_t)z * (Bz * 4096) + (size_t)b * 4096;
        gi += gr[j];
        gf += gr[1024 + j];
        gg += gr[2048 + j];
        go += gr[3072 + j];
    }
    float i = sigm(gi), f = sigm(gf), o = sigm(go);
    float c = f * c_prev[id] + i * tanhf(gg);
    float h = o * tanhf(c);
    h_scratch[b * h_stride + j] = h;
    h_out[id] = h;
    c_out[id] = c;
}

// ---------------------------------------------------------------------------
// launch
// ---------------------------------------------------------------------------
extern "C" void kernel_launch(void* const* d_in, const int* in_sizes, int n_in,
                              void* d_out, int out_size)
{
    const int*   token  = (const int*)  d_in[0];
    const float* hidden = (const float*)d_in[1];   // (2,64,1024)
    const float* cell   = (const float*)d_in[2];   // (2,64,1024)
    const float* enc    = (const float*)d_in[3];   // (128,64,2048)
    const float* emb    = (const float*)d_in[4];   // (32000,512)
    const float* W_enc  = (const float*)d_in[5];   // (512,2048)
    const float* W_dec  = (const float*)d_in[6];   // (512,1024)
    const float* v_w    = (const float*)d_in[7];   // (512)
    const float* W_ih0  = (const float*)d_in[8];   // (4096,2560)
    const float* W_hh0  = (const float*)d_in[9];   // (4096,1024)
    const float* b_ih0  = (const float*)d_in[10];
    const float* b_hh0  = (const float*)d_in[11];
    const float* W_ih1  = (const float*)d_in[12];  // (4096,1024)
    const float* W_hh1  = (const float*)d_in[13];  // (4096,1024)
    const float* b_ih1  = (const float*)d_in[14];
    const float* b_hh1  = (const float*)d_in[15];
    const float* fc_W   = (const float*)d_in[16];  // (32000,3072)
    const float* fc_b   = (const float*)d_in[17];  // (32000)

    float* scratch = nullptr;
    cudaGetSymbolAddress((void**)&scratch, g_scratch);

    float* energy   = scratch + OFF_ENERGY;
    float* dec_proj = scratch + OFF_DECP;    // DPSPLIT partials
    float* alpha    = scratch + OFF_ALPHA;
    float* x0       = scratch + OFF_X0;
    float* gates    = scratch + OFF_GATES;   // NSPLIT partials
    float* h0       = scratch + OFF_H0;
    float* fcin     = scratch + OFF_FCIN;

    float* out        = (float*)d_out;
    float* out_logits = out;                                   // 64*32000
    float* out_hidden = out + (size_t)Bz * Vv;                 // 2*64*1024
    float* out_cell   = out_hidden + 2 * Bz * Hd;              // 2*64*1024
    float* out_alpha  = out_cell + 2 * Bz * Hd;                // 64*128

    cudaFuncSetAttribute(GEMM_ENERGY, cudaFuncAttributeMaxDynamicSharedMemorySize, SMEM_ENERGY);
    cudaFuncSetAttribute(GEMM_SMALL,  cudaFuncAttributeMaxDynamicSharedMemorySize, SMEM_SMALL);

    // 1) embedding gather -> x0[:, :512]
    embed_kernel<<<(Bz * Ed) / 256, 256>>>(token, emb, x0);

    // 2) dec_proj partials = hidden[-1] @ W_dec^T   (split-K x4)
    //    T = 1024/32 = 32 tiles, 8 per z
    GEMM_SMALL<<<dim3(Ad / 128, 1, DPSPLIT), 256, SMEM_SMALL>>>(
        hidden + (size_t)Bz * Hd, W_dec, Hd,
        nullptr, nullptr, 0, nullptr, dec_proj, Ad, 32 / DPSPLIT, Bz * Ad);

    // 3) energy = enc @ W_enc^T                     (8192,512)
    GEMM_ENERGY<<<dim3(Ad / 128, (Sq * Bz) / 128, 1), 256, SMEM_ENERGY>>>(
        enc, W_enc, 2 * Hd,
        nullptr, nullptr, 0, nullptr, energy, Ad, 64, 0);

    // 4) fused score + softmax -> alpha
    score_softmax_kernel<<<Bz, 256>>>(energy, dec_proj, v_w, alpha, out_alpha);

    // 5) context -> x0[:,512:] and fcin[:,1024:]
    context_kernel<<<dim3(2048 / 256, Bz), 256>>>(alpha, enc, x0, fcin);

    // 6) gates0 partials = x0 @ W_ih0^T + hidden[0] @ W_hh0^T  (split-K x8)
    //    T = 80 + 32 = 112 tiles, 14 per z
    GEMM_SMALL<<<dim3(4096 / 128, 1, NSPLIT), 256, SMEM_SMALL>>>(
        x0, W_ih0, Ed + 2 * Hd,
        hidden, W_hh0, Hd, nullptr, gates, 4096, 112 / NSPLIT, Bz * 4096);

    // 7) LSTM cell 0 -> h0 (scratch), out_hidden[0], out_cell[0]
    cell_kernel<<<(Bz * Hd) / 256, 256>>>(gates, b_ih0, b_hh0, cell,
                                          h0, Hd, out_hidden, out_cell);

    // 8) gates1 partials = h0 @ W_ih1^T + hidden[1] @ W_hh1^T  (split-K x8)
    //    T = 32 + 32 = 64 tiles, 8 per z
    GEMM_SMALL<<<dim3(4096 / 128, 1, NSPLIT), 256, SMEM_SMALL>>>(
        h0, W_ih1, Hd,
        hidden + (size_t)Bz * Hd, W_hh1, Hd, nullptr, gates, 4096, 64 / NSPLIT, Bz * 4096);

    // 9) LSTM cell 1 -> h1 straight into fcin[:, :1024], out_hidden[1], out_cell[1]
    cell_kernel<<<(Bz * Hd) / 256, 256>>>(gates, b_ih1, b_hh1, cell + (size_t)Bz * Hd,
                                          fcin, 3 * Hd,
                                          out_hidden + (size_t)Bz * Hd,
                                          out_cell + (size_t)Bz * Hd);

    // 10) logits = fcin @ fc_W^T + fc_b            (64,32000)
    GEMM_SMALL<<<dim3(Vv / 128, 1, 1), 256, SMEM_SMALL>>>(
        fcin, fc_W, 3 * Hd,
        nullptr, nullptr, 0, fc_b, out_logits, Vv, 96, 0);
}